// round 6
// baseline (speedup 1.0000x reference)
#include <cuda_runtime.h>
#include <cuda_bf16.h>
#include <cstdint>

typedef unsigned long long ull;

// Problem constants
#define NMAX   50000
#define EMAX   800000
#define TOTMAX (EMAX + NMAX)
#define GRAPHS 256
#define HC     256      // H*C
#define KIN    300      // n_in
#define FOUT   768      // nout

// ---------------- scratch (device globals; no allocation) ----------------
__device__ float  g_h[NMAX * HC];          // node features after linear [N,256]
__device__ float  g_asrc[NMAX * 4];        // per-node src attention logits [N,4]
__device__ float  g_adst[NMAX * 4];        // per-node dst attention logits [N,4]
__device__ int    g_count[NMAX];           // in-degree (incl self-loop)
__device__ int    g_scanex[NMAX];          // per-chunk exclusive scan
__device__ int    g_bsum[64];              // chunk totals -> chunk offsets
__device__ int    g_rowoff[NMAX];          // CSR row offsets
__device__ int    g_cursor[NMAX];          // fill cursors
__device__ int    g_csrc[TOTMAX];          // CSR-ordered src ids
__device__ float4 g_cee[TOTMAX];           // CSR-ordered exp weights (per head)
__device__ float  g_pool[GRAPHS * HC];     // per-graph sums [G,256]
__device__ float  g_pooled[GRAPHS * HC];   // normalized pooled features
__device__ float  g_cnt[GRAPHS];           // per-graph node counts

// packed fp32x2 FMA (Blackwell FFMA2): d = a*b + d, two lanes at once
__device__ __forceinline__ void ffma2(ull& d, ull a, ull b) {
    asm("fma.rn.f32x2 %0, %1, %2, %0;" : "+l"(d) : "l"(a), "l"(b));
}

// ---------------- 0: init scratch ----------------
__global__ void init_kernel(int M) {
    int i = blockIdx.x * blockDim.x + threadIdx.x;
    if (i < M)            g_count[i] = 1;   // self-loop pre-counted
    if (i < GRAPHS * HC)  g_pool[i]  = 0.0f;
    if (i < GRAPHS)       g_cnt[i]   = 0.0f;
}

// ---------------- 1: h = x @ lin_w (+ fused attention dots), fp32x2 SIMT ----------------
// 128x128 tile, BK=8, 256 threads, 8x8 per thread. Accumulators packed along rows (i),
// B duplicated in smem so broadcast pairs load directly with LDS.128.
#define BM 128
#define BN 128
#define BK 8
__global__ __launch_bounds__(256, 2)
void gemm_h_kernel(const float* __restrict__ X,
                   const float* __restrict__ W,
                   const float* __restrict__ att_s,
                   const float* __restrict__ att_d,
                   int M) {
    __shared__ float As[BK][BM];
    __shared__ float Bs[BK][2 * BN];        // duplicated: Bs[k][2j]==Bs[k][2j+1]==b[j]
    __shared__ float s_as[BN], s_ad[BN];

    const int bx   = blockIdx.x;            // 0..1 -> N offset bx*128 (heads bx*2, bx*2+1)
    const int row0 = blockIdx.y * BM;
    const int tid  = threadIdx.x;
    const int tx   = tid & 15;
    const int ty   = tid >> 4;

    if (tid < BN) { s_as[tid] = att_s[bx * BN + tid]; s_ad[tid] = att_d[bx * BN + tid]; }

    // acc2[ah][bh][ip][j]: packed pair (rows ty*4+ip*2, ty*4+ip*2+1) x col j
    ull acc2[2][2][2][4];
#pragma unroll
    for (int a = 0; a < 2; a++)
#pragma unroll
        for (int b = 0; b < 2; b++)
#pragma unroll
            for (int ip = 0; ip < 2; ip++)
#pragma unroll
                for (int j = 0; j < 4; j++) acc2[a][b][ip][j] = 0ull;

    const int arow = tid >> 1;              // 0..127
    const int akb  = (tid & 1) * 4;         // 0 or 4
    const int bkk  = tid >> 5;              // 0..7
    const int bcol = (tid & 31) * 4;        // 0..124

    for (int k0 = 0; k0 < KIN; k0 += BK) {
        {
            int gr = row0 + arow, gk = k0 + akb;
            float4 a4 = make_float4(0.f, 0.f, 0.f, 0.f);
            if (gr < M && gk < KIN) a4 = *(const float4*)&X[gr * KIN + gk];
            As[akb + 0][arow] = a4.x;
            As[akb + 1][arow] = a4.y;
            As[akb + 2][arow] = a4.z;
            As[akb + 3][arow] = a4.w;
        }
        {
            int gk = k0 + bkk;
            float4 b4 = make_float4(0.f, 0.f, 0.f, 0.f);
            if (gk < KIN) b4 = *(const float4*)&W[gk * HC + bx * BN + bcol];
            *(float4*)&Bs[bkk][bcol * 2]     = make_float4(b4.x, b4.x, b4.y, b4.y);
            *(float4*)&Bs[bkk][bcol * 2 + 4] = make_float4(b4.z, b4.z, b4.w, b4.w);
        }
        __syncthreads();
#pragma unroll
        for (int kk = 0; kk < BK; kk++) {
            float4 a0 = *(const float4*)&As[kk][ty * 4];
            float4 a1 = *(const float4*)&As[kk][64 + ty * 4];
            ull a2[2][2];
            a2[0][0] = ((const ull*)&a0)[0]; a2[0][1] = ((const ull*)&a0)[1];
            a2[1][0] = ((const ull*)&a1)[0]; a2[1][1] = ((const ull*)&a1)[1];

            float4 bd0 = *(const float4*)&Bs[kk][tx * 8];
            float4 bd1 = *(const float4*)&Bs[kk][tx * 8 + 4];
            float4 bd2 = *(const float4*)&Bs[kk][128 + tx * 8];
            float4 bd3 = *(const float4*)&Bs[kk][128 + tx * 8 + 4];
            ull b2[2][4];
            b2[0][0] = ((const ull*)&bd0)[0]; b2[0][1] = ((const ull*)&bd0)[1];
            b2[0][2] = ((const ull*)&bd1)[0]; b2[0][3] = ((const ull*)&bd1)[1];
            b2[1][0] = ((const ull*)&bd2)[0]; b2[1][1] = ((const ull*)&bd2)[1];
            b2[1][2] = ((const ull*)&bd3)[0]; b2[1][3] = ((const ull*)&bd3)[1];

#pragma unroll
            for (int a = 0; a < 2; a++)
#pragma unroll
                for (int b = 0; b < 2; b++)
#pragma unroll
                    for (int ip = 0; ip < 2; ip++)
#pragma unroll
                        for (int j = 0; j < 4; j++)
                            ffma2(acc2[a][b][ip][j], a2[a][ip], b2[b][j]);
        }
        __syncthreads();
    }

    // epilogue: unpack pairs, store h + fused attention dots
#pragma unroll
    for (int a = 0; a < 2; a++) {
#pragma unroll
        for (int ip = 0; ip < 2; ip++) {
#pragma unroll
            for (int ih = 0; ih < 2; ih++) {             // which half of the pair
                int gr = row0 + a * 64 + ty * 4 + ip * 2 + ih;
                bool ok = gr < M;
#pragma unroll
                for (int b = 0; b < 2; b++) {
                    float v0 = ((const float*)&acc2[a][b][ip][0])[ih];
                    float v1 = ((const float*)&acc2[a][b][ip][1])[ih];
                    float v2 = ((const float*)&acc2[a][b][ip][2])[ih];
                    float v3 = ((const float*)&acc2[a][b][ip][3])[ih];
                    if (ok) {
                        *(float4*)&g_h[gr * HC + bx * BN + b * 64 + tx * 4] =
                            make_float4(v0, v1, v2, v3);
                    }
                    float s = v0 * s_as[b * 64 + tx * 4]     + v1 * s_as[b * 64 + tx * 4 + 1]
                            + v2 * s_as[b * 64 + tx * 4 + 2] + v3 * s_as[b * 64 + tx * 4 + 3];
                    float d = v0 * s_ad[b * 64 + tx * 4]     + v1 * s_ad[b * 64 + tx * 4 + 1]
                            + v2 * s_ad[b * 64 + tx * 4 + 2] + v3 * s_ad[b * 64 + tx * 4 + 3];
#pragma unroll
                    for (int off = 8; off > 0; off >>= 1) {
                        s += __shfl_down_sync(0xffffffffu, s, off, 16);
                        d += __shfl_down_sync(0xffffffffu, d, off, 16);
                    }
                    if (ok && tx == 0) {
                        g_asrc[gr * 4 + bx * 2 + b] = s;
                        g_adst[gr * 4 + bx * 2 + b] = d;
                    }
                }
            }
        }
    }
}

// ---------------- 2: degree count (dst only; self-loops pre-counted) ----------------
__global__ void edge_count_kernel(const int* __restrict__ ei, int E) {
    int i = blockIdx.x * blockDim.x + threadIdx.x;
    if (i >= E) return;
    atomicAdd(&g_count[ei[E + i]], 1);
}

// ---------------- 3: 2-level exclusive scan of g_count ----------------
__global__ void scan1_kernel(int M) {                     // block=1024
    __shared__ int sh[2][1024];
    int i = blockIdx.x * 1024 + threadIdx.x;
    int v = (i < M) ? g_count[i] : 0;
    int buf = 0;
    sh[0][threadIdx.x] = v;
    __syncthreads();
#pragma unroll
    for (int off = 1; off < 1024; off <<= 1) {
        int nv = sh[buf][threadIdx.x];
        if (threadIdx.x >= off) nv += sh[buf][threadIdx.x - off];
        sh[1 - buf][threadIdx.x] = nv;
        buf = 1 - buf;
        __syncthreads();
    }
    int incl = sh[buf][threadIdx.x];
    if (i < M) g_scanex[i] = incl - v;
    if (threadIdx.x == 1023) g_bsum[blockIdx.x] = incl;
}

__global__ void scan2_kernel(int nb) {                    // 1 thread
    int run = 0;
    for (int b = 0; b < nb; b++) { int t = g_bsum[b]; g_bsum[b] = run; run += t; }
}

__global__ void scan3_kernel(int M) {
    int i = blockIdx.x * blockDim.x + threadIdx.x;
    if (i >= M) return;
    int off = g_scanex[i] + g_bsum[i >> 10];
    g_rowoff[i] = off;
    g_cursor[i] = off;
}

// ---------------- 4: CSR fill (recomputes leaky+exp; no g_e round-trip) ----------------
__global__ void edge_fill_kernel(const int* __restrict__ ei, int E, int M) {
    int i = blockIdx.x * blockDim.x + threadIdx.x;
    int total = E + M;
    if (i >= total) return;
    int s, d;
    if (i < E) { s = ei[i]; d = ei[E + i]; }
    else       { s = d = i - E; }
    float4 as = ((const float4*)g_asrc)[s];
    float4 ad = ((const float4*)g_adst)[d];
    float e0 = as.x + ad.x, e1 = as.y + ad.y, e2 = as.z + ad.z, e3 = as.w + ad.w;
    e0 = e0 > 0.f ? e0 : 0.2f * e0;
    e1 = e1 > 0.f ? e1 : 0.2f * e1;
    e2 = e2 > 0.f ? e2 : 0.2f * e2;
    e3 = e3 > 0.f ? e3 : 0.2f * e3;
    float4 ee = make_float4(__expf(e0), __expf(e1), __expf(e2), __expf(e3));
    int pos = atomicAdd(&g_cursor[d], 1);
    g_csrc[pos] = s;
    g_cee[pos]  = ee;
}

// ---------------- 5: gather-aggregate (warp per node) + denom + bias + leaky + pool ----------------
__global__ void aggregate_kernel(const int* __restrict__ batch,
                                 const float* __restrict__ bias, int M) {
    int w = blockIdx.x * (blockDim.x >> 5) + (threadIdx.x >> 5);
    if (w >= M) return;
    int lane = threadIdx.x & 31;
    int start = g_rowoff[w];
    int end   = start + g_count[w];
    int hsel  = lane >> 3;                      // head for this thread's 8 channels

    float acc[8];
#pragma unroll
    for (int k = 0; k < 8; k++) acc[k] = 0.0f;
    float wsum = 0.0f;

    int src = 0; float4 ee = make_float4(0, 0, 0, 0);
    if (start < end) { src = g_csrc[start]; ee = g_cee[start]; }
    for (int j = start; j < end; j++) {
        int nsrc = 0; float4 nee = ee;
        if (j + 1 < end) { nsrc = g_csrc[j + 1]; nee = g_cee[j + 1]; }
        const float4* hp = (const float4*)&g_h[(long long)src * HC + lane * 8];
        float4 h0 = hp[0], h1 = hp[1];
        float wgt = (hsel == 0) ? ee.x : (hsel == 1) ? ee.y : (hsel == 2) ? ee.z : ee.w;
        wsum += wgt;
        acc[0] += h0.x * wgt; acc[1] += h0.y * wgt;
        acc[2] += h0.z * wgt; acc[3] += h0.w * wgt;
        acc[4] += h1.x * wgt; acc[5] += h1.y * wgt;
        acc[6] += h1.z * wgt; acc[7] += h1.w * wgt;
        src = nsrc; ee = nee;
    }

    float inv = 1.0f / wsum;
    int b = batch[w];
    float* pp = &g_pool[b * HC + lane * 8];
#pragma unroll
    for (int k = 0; k < 8; k++) {
        float v = acc[k] * inv + bias[lane * 8 + k];
        v = v > 0.f ? v : 0.01f * v;
        atomicAdd(&pp[k], v);
    }
    if (lane == 0) atomicAdd(&g_cnt[b], 1.0f);
}

// ---------------- 6a: normalize pooled sums ----------------
__global__ void pool_norm_kernel() {
    int i = blockIdx.x * blockDim.x + threadIdx.x;
    if (i >= GRAPHS * HC) return;
    int g = i >> 8;
    g_pooled[i] = g_pool[i] / fmaxf(g_cnt[g], 1.0f);
}

// ---------------- 6b: out = pooled @ fc1_w + fc1_b, tiled ----------------
#define FBM 32
#define FBN 64
#define SPP 260
__global__ __launch_bounds__(256)
void fc_kernel(const float* __restrict__ fc1_w,
               const float* __restrict__ fc1_b,
               float* __restrict__ out) {
    __shared__ float sp[FBM * SPP];
    __shared__ float sw[32][FBN];
    const int g0  = blockIdx.y * FBM;
    const int n0  = blockIdx.x * FBN;
    const int tid = threadIdx.x;

#pragma unroll
    for (int it = 0; it < 8; it++) {
        int i = tid + it * 256;
        int r = i >> 6;
        int c = (i & 63) * 4;
        *(float4*)&sp[r * SPP + c] = *(const float4*)&g_pooled[(g0 + r) * HC + c];
    }

    const int row = tid >> 3;
    const int cg  = (tid & 7) * 8;
    float acc[8];
#pragma unroll
    for (int j = 0; j < 8; j++) acc[j] = 0.0f;

    for (int k0 = 0; k0 < HC; k0 += 32) {
        __syncthreads();
#pragma unroll
        for (int it = 0; it < 2; it++) {
            int i = tid + it * 256;
            int r = i >> 4;
            int c = (i & 15) * 4;
            *(float4*)&sw[r][c] = *(const float4*)&fc1_w[(k0 + r) * FOUT + n0 + c];
        }
        __syncthreads();
#pragma unroll
        for (int kk = 0; kk < 32; kk++) {
            float p = sp[row * SPP + k0 + kk];
            float4 w0 = *(const float4*)&sw[kk][cg];
            float4 w1 = *(const float4*)&sw[kk][cg + 4];
            acc[0] += p * w0.x; acc[1] += p * w0.y;
            acc[2] += p * w0.z; acc[3] += p * w0.w;
            acc[4] += p * w1.x; acc[5] += p * w1.y;
            acc[6] += p * w1.z; acc[7] += p * w1.w;
        }
    }
#pragma unroll
    for (int j = 0; j < 8; j++) acc[j] += fc1_b[n0 + cg + j];
    *(float4*)&out[(g0 + row) * FOUT + n0 + cg]     = make_float4(acc[0], acc[1], acc[2], acc[3]);
    *(float4*)&out[(g0 + row) * FOUT + n0 + cg + 4] = make_float4(acc[4], acc[5], acc[6], acc[7]);
}

// ---------------- launch ----------------
extern "C" void kernel_launch(void* const* d_in, const int* in_sizes, int n_in,
                              void* d_out, int out_size) {
    const float* x     = (const float*)d_in[0];
    const int*   ei    = (const int*)d_in[1];
    const int*   batch = (const int*)d_in[2];
    const float* lin_w = (const float*)d_in[3];
    const float* att_s = (const float*)d_in[4];
    const float* att_d = (const float*)d_in[5];
    const float* bias  = (const float*)d_in[6];
    const float* fc1_w = (const float*)d_in[7];
    const float* fc1_b = (const float*)d_in[8];
    float* out = (float*)d_out;

    int M = in_sizes[2];       // nodes
    int E = in_sizes[1] / 2;   // edges
    int total = E + M;

    int initN = M > GRAPHS * HC ? M : GRAPHS * HC;
    init_kernel<<<(initN + 255) / 256, 256>>>(M);

    dim3 ggrid(2, (M + BM - 1) / BM);
    gemm_h_kernel<<<ggrid, 256>>>(x, lin_w, att_s, att_d, M);

    edge_count_kernel<<<(E + 255) / 256, 256>>>(ei, E);

    int nb = (M + 1023) / 1024;
    scan1_kernel<<<nb, 1024>>>(M);
    scan2_kernel<<<1, 1>>>(nb);
    scan3_kernel<<<(M + 255) / 256, 256>>>(M);

    edge_fill_kernel<<<(total + 255) / 256, 256>>>(ei, E, M);

    aggregate_kernel<<<(M * 32 + 255) / 256, 256>>>(batch, bias, M);

    pool_norm_kernel<<<(GRAPHS * HC + 255) / 256, 256>>>();

    dim3 fgrid(FOUT / FBN, GRAPHS / FBM);
    fc_kernel<<<fgrid, 256>>>(fc1_w, fc1_b, out);
}

// round 7
// speedup vs baseline: 1.3269x; 1.3269x over previous
#include <cuda_runtime.h>
#include <cuda_bf16.h>

// Problem constants
#define NMAX   50000
#define EMAX   800000
#define TOTMAX (EMAX + NMAX)
#define GRAPHS 256
#define HC     256      // H*C
#define KIN    300      // n_in
#define FOUT   768      // nout

// ---------------- scratch (device globals; no allocation) ----------------
__device__ float  g_h[NMAX * HC];          // node features after linear [N,256]
__device__ float  g_asrc[NMAX * 4];        // per-node src attention logits [N,4]
__device__ float  g_adst[NMAX * 4];        // per-node dst attention logits [N,4]
__device__ int    g_count[NMAX];           // in-degree (incl self-loop)
__device__ int    g_scanex[NMAX];          // per-chunk exclusive scan
__device__ int    g_bsum[64];              // chunk totals -> chunk offsets
__device__ int    g_rowoff[NMAX];          // CSR row offsets
__device__ int    g_cursor[NMAX];          // fill cursors
__device__ int    g_csrc[TOTMAX];          // CSR-ordered src ids
__device__ float4 g_cee[TOTMAX];           // CSR-ordered exp weights (per head)
__device__ float  g_pool[GRAPHS * HC];     // per-graph sums [G,256]
__device__ float  g_pooled[GRAPHS * HC];   // normalized pooled features
__device__ float  g_cnt[GRAPHS];           // per-graph node counts

// ---------------- 0: init scratch ----------------
__global__ void init_kernel(int M) {
    int i = blockIdx.x * blockDim.x + threadIdx.x;
    if (i < M)            g_count[i] = 1;   // self-loop pre-counted
    if (i < GRAPHS * HC)  g_pool[i]  = 0.0f;
    if (i < GRAPHS)       g_cnt[i]   = 0.0f;
}

// ---------------- 1: h = x @ lin_w (+ fused attention dots), fp32 SIMT ----------------
// 128x128 tile, BK=8, 256 threads, 8x8 per thread (2x2 blocks of 4x4).  [R3-proven]
#define BM 128
#define BN 128
#define BK 8
__global__ __launch_bounds__(256, 2)
void gemm_h_kernel(const float* __restrict__ X,
                   const float* __restrict__ W,
                   const float* __restrict__ att_s,
                   const float* __restrict__ att_d,
                   int M) {
    __shared__ float As[BK][BM];
    __shared__ float Bs[BK][BN];
    __shared__ float s_as[BN], s_ad[BN];

    const int bx   = blockIdx.x;              // 0..1 -> N offset bx*128 (heads bx*2, bx*2+1)
    const int row0 = blockIdx.y * BM;
    const int tid  = threadIdx.x;
    const int tx   = tid & 15;
    const int ty   = tid >> 4;

    if (tid < BN) { s_as[tid] = att_s[bx * BN + tid]; s_ad[tid] = att_d[bx * BN + tid]; }

    float acc[2][2][4][4];
#pragma unroll
    for (int a = 0; a < 2; a++)
#pragma unroll
        for (int b = 0; b < 2; b++)
#pragma unroll
            for (int i = 0; i < 4; i++)
#pragma unroll
                for (int j = 0; j < 4; j++) acc[a][b][i][j] = 0.0f;

    const int arow  = tid >> 1;             // 0..127
    const int akb   = (tid & 1) * 4;        // 0 or 4
    const int bkk   = tid >> 5;             // 0..7
    const int bcol  = (tid & 31) * 4;       // 0..124

    for (int k0 = 0; k0 < KIN; k0 += BK) {
        {
            int gr = row0 + arow, gk = k0 + akb;
            float4 a4 = make_float4(0.f, 0.f, 0.f, 0.f);
            if (gr < M && gk < KIN) a4 = *(const float4*)&X[gr * KIN + gk];
            As[akb + 0][arow] = a4.x;
            As[akb + 1][arow] = a4.y;
            As[akb + 2][arow] = a4.z;
            As[akb + 3][arow] = a4.w;
        }
        {
            int gk = k0 + bkk;
            float4 b4 = make_float4(0.f, 0.f, 0.f, 0.f);
            if (gk < KIN) b4 = *(const float4*)&W[gk * HC + bx * BN + bcol];
            *(float4*)&Bs[bkk][bcol] = b4;
        }
        __syncthreads();
#pragma unroll
        for (int kk = 0; kk < BK; kk++) {
            float4 a0 = *(const float4*)&As[kk][ty * 4];
            float4 a1 = *(const float4*)&As[kk][64 + ty * 4];
            float4 b0 = *(const float4*)&Bs[kk][tx * 4];
            float4 b1 = *(const float4*)&Bs[kk][64 + tx * 4];
            float av[2][4] = {{a0.x, a0.y, a0.z, a0.w}, {a1.x, a1.y, a1.z, a1.w}};
            float bv[2][4] = {{b0.x, b0.y, b0.z, b0.w}, {b1.x, b1.y, b1.z, b1.w}};
#pragma unroll
            for (int a = 0; a < 2; a++)
#pragma unroll
                for (int b = 0; b < 2; b++)
#pragma unroll
                    for (int i = 0; i < 4; i++)
#pragma unroll
                        for (int j = 0; j < 4; j++)
                            acc[a][b][i][j] += av[a][i] * bv[b][j];
        }
        __syncthreads();
    }

    // epilogue: store h + fused attention dots
#pragma unroll
    for (int a = 0; a < 2; a++) {
#pragma unroll
        for (int i = 0; i < 4; i++) {
            int gr = row0 + a * 64 + ty * 4 + i;
            bool ok = gr < M;
#pragma unroll
            for (int b = 0; b < 2; b++) {
                if (ok) {
                    *(float4*)&g_h[gr * HC + bx * BN + b * 64 + tx * 4] =
                        make_float4(acc[a][b][i][0], acc[a][b][i][1],
                                    acc[a][b][i][2], acc[a][b][i][3]);
                }
                float s = 0.f, d = 0.f;
#pragma unroll
                for (int j = 0; j < 4; j++) {
                    s += acc[a][b][i][j] * s_as[b * 64 + tx * 4 + j];
                    d += acc[a][b][i][j] * s_ad[b * 64 + tx * 4 + j];
                }
#pragma unroll
                for (int off = 8; off > 0; off >>= 1) {
                    s += __shfl_down_sync(0xffffffffu, s, off, 16);
                    d += __shfl_down_sync(0xffffffffu, d, off, 16);
                }
                if (ok && tx == 0) {
                    g_asrc[gr * 4 + bx * 2 + b] = s;
                    g_adst[gr * 4 + bx * 2 + b] = d;
                }
            }
        }
    }
}

// ---------------- 2: degree count (dst only; self-loops pre-counted) ----------------
__global__ void edge_count_kernel(const int* __restrict__ ei, int E) {
    int i = blockIdx.x * blockDim.x + threadIdx.x;
    if (i >= E) return;
    atomicAdd(&g_count[ei[E + i]], 1);
}

// ---------------- 3: 2-level exclusive scan of g_count ----------------
__global__ void scan1_kernel(int M) {                     // block=1024
    __shared__ int sh[2][1024];
    int i = blockIdx.x * 1024 + threadIdx.x;
    int v = (i < M) ? g_count[i] : 0;
    int buf = 0;
    sh[0][threadIdx.x] = v;
    __syncthreads();
#pragma unroll
    for (int off = 1; off < 1024; off <<= 1) {
        int nv = sh[buf][threadIdx.x];
        if (threadIdx.x >= off) nv += sh[buf][threadIdx.x - off];
        sh[1 - buf][threadIdx.x] = nv;
        buf = 1 - buf;
        __syncthreads();
    }
    int incl = sh[buf][threadIdx.x];
    if (i < M) g_scanex[i] = incl - v;
    if (threadIdx.x == 1023) g_bsum[blockIdx.x] = incl;
}

__global__ void scan2_kernel(int nb) {                    // 1 thread
    int run = 0;
    for (int b = 0; b < nb; b++) { int t = g_bsum[b]; g_bsum[b] = run; run += t; }
}

__global__ void scan3_kernel(int M) {
    int i = blockIdx.x * blockDim.x + threadIdx.x;
    if (i >= M) return;
    int off = g_scanex[i] + g_bsum[i >> 10];
    g_rowoff[i] = off;
    g_cursor[i] = off;
}

// ---------------- 4: CSR fill (recomputes leaky+exp; no g_e round-trip) ----------------
__global__ void edge_fill_kernel(const int* __restrict__ ei, int E, int M) {
    int i = blockIdx.x * blockDim.x + threadIdx.x;
    int total = E + M;
    if (i >= total) return;
    int s, d;
    if (i < E) { s = ei[i]; d = ei[E + i]; }
    else       { s = d = i - E; }
    float4 as = ((const float4*)g_asrc)[s];
    float4 ad = ((const float4*)g_adst)[d];
    float e0 = as.x + ad.x, e1 = as.y + ad.y, e2 = as.z + ad.z, e3 = as.w + ad.w;
    e0 = e0 > 0.f ? e0 : 0.2f * e0;
    e1 = e1 > 0.f ? e1 : 0.2f * e1;
    e2 = e2 > 0.f ? e2 : 0.2f * e2;
    e3 = e3 > 0.f ? e3 : 0.2f * e3;
    float4 ee = make_float4(__expf(e0), __expf(e1), __expf(e2), __expf(e3));
    int pos = atomicAdd(&g_cursor[d], 1);
    g_csrc[pos] = s;
    g_cee[pos]  = ee;
}

// ---------------- 5: gather-aggregate (warp per node) + denom + bias + leaky + pool ----------------
__global__ void aggregate_kernel(const int* __restrict__ batch,
                                 const float* __restrict__ bias, int M) {
    int w = blockIdx.x * (blockDim.x >> 5) + (threadIdx.x >> 5);
    if (w >= M) return;
    int lane = threadIdx.x & 31;
    int start = g_rowoff[w];
    int end   = start + g_count[w];
    int hsel  = lane >> 3;                      // head for this thread's 8 channels

    float acc[8];
#pragma unroll
    for (int k = 0; k < 8; k++) acc[k] = 0.0f;
    float wsum = 0.0f;

    int src = 0; float4 ee = make_float4(0, 0, 0, 0);
    if (start < end) { src = g_csrc[start]; ee = g_cee[start]; }
    for (int j = start; j < end; j++) {
        int nsrc = 0; float4 nee = ee;
        if (j + 1 < end) { nsrc = g_csrc[j + 1]; nee = g_cee[j + 1]; }
        const float4* hp = (const float4*)&g_h[(long long)src * HC + lane * 8];
        float4 h0 = hp[0], h1 = hp[1];
        float wgt = (hsel == 0) ? ee.x : (hsel == 1) ? ee.y : (hsel == 2) ? ee.z : ee.w;
        wsum += wgt;
        acc[0] += h0.x * wgt; acc[1] += h0.y * wgt;
        acc[2] += h0.z * wgt; acc[3] += h0.w * wgt;
        acc[4] += h1.x * wgt; acc[5] += h1.y * wgt;
        acc[6] += h1.z * wgt; acc[7] += h1.w * wgt;
        src = nsrc; ee = nee;
    }

    float inv = 1.0f / wsum;
    int b = batch[w];
    float* pp = &g_pool[b * HC + lane * 8];
#pragma unroll
    for (int k = 0; k < 8; k++) {
        float v = acc[k] * inv + bias[lane * 8 + k];
        v = v > 0.f ? v : 0.01f * v;
        atomicAdd(&pp[k], v);
    }
    if (lane == 0) atomicAdd(&g_cnt[b], 1.0f);
}

// ---------------- 6a: normalize pooled sums ----------------
__global__ void pool_norm_kernel() {
    int i = blockIdx.x * blockDim.x + threadIdx.x;
    if (i >= GRAPHS * HC) return;
    int g = i >> 8;
    g_pooled[i] = g_pool[i] / fmaxf(g_cnt[g], 1.0f);
}

// ---------------- 6b: out = pooled @ fc1_w + fc1_b, tiled ----------------
#define FBM 32
#define FBN 64
#define SPP 260
__global__ __launch_bounds__(256)
void fc_kernel(const float* __restrict__ fc1_w,
               const float* __restrict__ fc1_b,
               float* __restrict__ out) {
    __shared__ float sp[FBM * SPP];
    __shared__ float sw[32][FBN];
    const int g0  = blockIdx.y * FBM;
    const int n0  = blockIdx.x * FBN;
    const int tid = threadIdx.x;

#pragma unroll
    for (int it = 0; it < 8; it++) {
        int i = tid + it * 256;
        int r = i >> 6;
        int c = (i & 63) * 4;
        *(float4*)&sp[r * SPP + c] = *(const float4*)&g_pooled[(g0 + r) * HC + c];
    }

    const int row = tid >> 3;
    const int cg  = (tid & 7) * 8;
    float acc[8];
#pragma unroll
    for (int j = 0; j < 8; j++) acc[j] = 0.0f;

    for (int k0 = 0; k0 < HC; k0 += 32) {
        __syncthreads();
#pragma unroll
        for (int it = 0; it < 2; it++) {
            int i = tid + it * 256;
            int r = i >> 4;
            int c = (i & 15) * 4;
            *(float4*)&sw[r][c] = *(const float4*)&fc1_w[(k0 + r) * FOUT + n0 + c];
        }
        __syncthreads();
#pragma unroll
        for (int kk = 0; kk < 32; kk++) {
            float p = sp[row * SPP + k0 + kk];
            float4 w0 = *(const float4*)&sw[kk][cg];
            float4 w1 = *(const float4*)&sw[kk][cg + 4];
            acc[0] += p * w0.x; acc[1] += p * w0.y;
            acc[2] += p * w0.z; acc[3] += p * w0.w;
            acc[4] += p * w1.x; acc[5] += p * w1.y;
            acc[6] += p * w1.z; acc[7] += p * w1.w;
        }
    }
#pragma unroll
    for (int j = 0; j < 8; j++) acc[j] += fc1_b[n0 + cg + j];
    *(float4*)&out[(g0 + row) * FOUT + n0 + cg]     = make_float4(acc[0], acc[1], acc[2], acc[3]);
    *(float4*)&out[(g0 + row) * FOUT + n0 + cg + 4] = make_float4(acc[4], acc[5], acc[6], acc[7]);
}

// ---------------- launch ----------------
extern "C" void kernel_launch(void* const* d_in, const int* in_sizes, int n_in,
                              void* d_out, int out_size) {
    const float* x     = (const float*)d_in[0];
    const int*   ei    = (const int*)d_in[1];
    const int*   batch = (const int*)d_in[2];
    const float* lin_w = (const float*)d_in[3];
    const float* att_s = (const float*)d_in[4];
    const float* att_d = (const float*)d_in[5];
    const float* bias  = (const float*)d_in[6];
    const float* fc1_w = (const float*)d_in[7];
    const float* fc1_b = (const float*)d_in[8];
    float* out = (float*)d_out;

    int M = in_sizes[2];       // nodes
    int E = in_sizes[1] / 2;   // edges
    int total = E + M;

    int initN = M > GRAPHS * HC ? M : GRAPHS * HC;
    init_kernel<<<(initN + 255) / 256, 256>>>(M);

    dim3 ggrid(2, (M + BM - 1) / BM);
    gemm_h_kernel<<<ggrid, 256>>>(x, lin_w, att_s, att_d, M);

    edge_count_kernel<<<(E + 255) / 256, 256>>>(ei, E);

    int nb = (M + 1023) / 1024;
    scan1_kernel<<<nb, 1024>>>(M);
    scan2_kernel<<<1, 1>>>(nb);
    scan3_kernel<<<(M + 255) / 256, 256>>>(M);

    edge_fill_kernel<<<(total + 255) / 256, 256>>>(ei, E, M);

    aggregate_kernel<<<(M * 32 + 255) / 256, 256>>>(batch, bias, M);

    pool_norm_kernel<<<(GRAPHS * HC + 255) / 256, 256>>>();

    dim3 fgrid(FOUT / FBN, GRAPHS / FBM);
    fc_kernel<<<fgrid, 256>>>(fc1_w, fc1_b, out);
}